// round 14
// baseline (speedup 1.0000x reference)
#include <cuda_runtime.h>

#define BB 128
#define NN 16384
#define HH 512
#define WW 512
#define NPIX ((size_t)BB * HH * WW)        // 33,554,432 pixels
#define PHASE_FRAMES 16                    // 16MB image slice
#define NPHASE (BB / PHASE_FRAMES)         // 8 phases
#define PHASE_V8 ((unsigned)PHASE_FRAMES * HH * WW / 8)    // 524,288 v8 groups

#define ZERO_BLOCKS  256                   // 256*256 thr * 8 v8 = 524288 ✓
#define SPLAT_BLOCKS 128                   // 128*256 thr * 8 pts = 262144 ✓
#define LOSS_BLOCKS  512                   // 512*256 thr * 4 v8 = 524288 ✓
#define TOTAL_BLOCKS (ZERO_BLOCKS + SPLAT_BLOCKS + LOSS_BLOCKS)   // 896; 2:1:4 per 7

// Scratch image. Zeroed slice-by-slice each call (pipeline stage 0); loss
// DISCARDS img lines from L2 after reading (no writeback).
__device__ __align__(128) float g_img[BB * HH * WW];
__device__ double g_sum;

// ---- 256-bit global access helpers (sm_100+: LDG.E.256 / STG.256) ----
__device__ __forceinline__ void ldg_cs_v8(const float* p, float* r) {
    asm volatile("ld.global.cs.v8.f32 {%0,%1,%2,%3,%4,%5,%6,%7}, [%8];"
        : "=f"(r[0]), "=f"(r[1]), "=f"(r[2]), "=f"(r[3]),
          "=f"(r[4]), "=f"(r[5]), "=f"(r[6]), "=f"(r[7])
        : "l"(p));
}
__device__ __forceinline__ void ldg_cg_v8(const float* p, float* r) {
    asm volatile("ld.global.cg.v8.f32 {%0,%1,%2,%3,%4,%5,%6,%7}, [%8];"
        : "=f"(r[0]), "=f"(r[1]), "=f"(r[2]), "=f"(r[3]),
          "=f"(r[4]), "=f"(r[5]), "=f"(r[6]), "=f"(r[7])
        : "l"(p));
}
__device__ __forceinline__ void stg_cg_v8_zero(float* p) {
    float z = 0.0f;
    asm volatile("st.global.cg.v8.f32 [%0], {%1,%2,%3,%4,%5,%6,%7,%8};"
        :: "l"(p), "f"(z), "f"(z), "f"(z), "f"(z), "f"(z), "f"(z), "f"(z), "f"(z)
        : "memory");
}

// Zero one slice with 256-bit full-line stores.
__device__ __forceinline__ void zero_body(int frame_base, int zblk) {
    float* base = g_img + (size_t)frame_base * HH * WW;
    unsigned id = (unsigned)zblk * 256u + threadIdx.x;     // 0 .. 65535
    #pragma unroll
    for (int k = 0; k < 8; k++)
        stg_cg_v8_zero(base + ((size_t)(id + k * 65536u)) * 8);
}

// Splat 8 points per thread using 3 × 256-bit loads (24 floats).
__device__ __forceinline__ void splat_body(const float* __restrict__ pts,
                                           int frame_base, int sblk) {
    int t8 = sblk * 256 + threadIdx.x;         // 0 .. 32767
    int p0 = t8 * 8;                           // point index within phase
    const float* base = pts + ((size_t)frame_base * NN + p0) * 3;

    float f[24];
    ldg_cs_v8(base,      f);
    ldg_cs_v8(base + 8,  f + 8);
    ldg_cs_v8(base + 16, f + 16);

    // 8 consecutive points share a frame (8 | NN)
    int b = frame_base + p0 / NN;
    float* img = g_img + (size_t)b * HH * WW;

    #pragma unroll
    for (int j = 0; j < 8; j++) {
        float x     = f[3 * j + 0];
        float y     = f[3 * j + 1];
        float inten = f[3 * j + 2];
        x = fminf(fmaxf(x, 0.0f), (float)(WW - 1));
        y = fminf(fmaxf(y, 0.0f), (float)(HH - 1));
        float x0f = floorf(x);
        float y0f = floorf(y);
        float fx = x - x0f;
        float fy = y - y0f;
        int x0 = (int)x0f;
        int y0 = (int)y0f;
        int x1 = min(x0 + 1, WW - 1);
        int y1 = min(y0 + 1, HH - 1);
        float w00 = inten * (1.0f - fx) * (1.0f - fy);
        float w01 = inten * fx * (1.0f - fy);
        float w10 = inten * (1.0f - fx) * fy;
        float w11 = inten * fx * fy;
        atomicAdd(&img[y0 * WW + x0], w00);   // REDG on L2-resident zeroed lines
        atomicAdd(&img[y0 * WW + x1], w01);
        atomicAdd(&img[y1 * WW + x0], w10);
        atomicAdd(&img[y1 * WW + x1], w11);
    }
}

__device__ __forceinline__ void loss_body(const float* __restrict__ tgt,
                                          int frame_base, int lblk) {
    const size_t base = (size_t)frame_base * HH * WW;
    float* imgb = g_img + base;
    const float* tgtb = tgt + base;

    unsigned id = (unsigned)lblk * 256u + threadIdx.x;     // 0 .. 131071
    const unsigned stride = LOSS_BLOCKS * 256u;            // 131072

    float acc = 0.0f;
    // Process v8 slots in pairs: 4 × 256-bit loads in flight per batch.
    #pragma unroll
    for (int kk = 0; kk < 2; kk++) {
        float a0[8], a1[8], t0[8], t1[8];
        size_t o0 = ((size_t)(id + (2 * kk + 0) * stride)) * 8;
        size_t o1 = ((size_t)(id + (2 * kk + 1) * stride)) * 8;
        ldg_cg_v8(imgb + o0, a0);    // L2-hot from splat
        ldg_cg_v8(imgb + o1, a1);
        ldg_cs_v8(tgtb + o0, t0);    // pure stream, evict-first
        ldg_cs_v8(tgtb + o1, t1);
        #pragma unroll
        for (int j = 0; j < 8; j++) {
            float d0 = a0[j] - t0[j];
            float d1 = a1[j] - t1[j];
            acc = fmaf(d0, d0, acc);
            acc = fmaf(d1, d1, acc);
        }
    }

    // Drop img lines from L2 WITHOUT writeback (data already consumed).
    // 4 consecutive threads (32B each) cover one 128B line; (t&3)==0 issues.
    if ((threadIdx.x & 3) == 0) {
        #pragma unroll
        for (int k = 0; k < 4; k++) {
            const float* p = imgb + ((size_t)(id + k * stride)) * 8;
            asm volatile("discard.global.L2 [%0], 128;" :: "l"(p) : "memory");
        }
    }

    // block reduce in double
    double dacc = (double)acc;
    __shared__ double sred[8];
    int lane = threadIdx.x & 31;
    int wid  = threadIdx.x >> 5;
    #pragma unroll
    for (int off = 16; off > 0; off >>= 1)
        dacc += __shfl_down_sync(0xFFFFFFFFu, dacc, off);
    if (lane == 0) sred[wid] = dacc;
    __syncthreads();
    if (wid == 0) {
        double v = (lane < 8) ? sred[lane] : 0.0;
        #pragma unroll
        for (int off = 4; off > 0; off >>= 1)
            v += __shfl_down_sync(0xFFFFFFFFu, v, off);
        if (lane == 0) atomicAdd(&g_sum, v);
    }
}

// Interleaved 3-stage pipeline: per 7-block group, 2 zero / 1 splat / 4 loss.
__global__ void __launch_bounds__(256, 5) pipe_kernel(const float* __restrict__ pts,
                                                      const float* __restrict__ tgt,
                                                      int zero_phase, int splat_phase,
                                                      int loss_phase) {
    int blk = blockIdx.x;
    int s = blk / 7;
    int r = blk - 7 * s;
    if (r < 2) {
        if (zero_phase >= 0)
            zero_body(zero_phase * PHASE_FRAMES, s * 2 + r);
    } else if (r == 2) {
        if (splat_phase >= 0)
            splat_body(pts, splat_phase * PHASE_FRAMES, s);
    } else {
        if (loss_phase >= 0)
            loss_body(tgt, loss_phase * PHASE_FRAMES, s * 4 + (r - 3));
    }
}

__global__ void finalize_kernel(float* __restrict__ out) {
    out[0] = (float)(g_sum / (double)NPIX);
    g_sum = 0.0;   // reset for next replay (module load provides the first zero)
}

extern "C" void kernel_launch(void* const* d_in, const int* in_sizes, int n_in,
                              void* d_out, int out_size) {
    const float* pts = (const float*)d_in[0];       // [B, N, 3]
    const float* tgt = (const float*)d_in[1];       // [B, H, W]
    float* out = (float*)d_out;

    // Launch k: zero(k), splat(k-1), loss(k-2); k = 0 .. NPHASE+1
    for (int k = 0; k < NPHASE + 2; k++) {
        int zp = (k < NPHASE)                ? k     : -1;
        int sp = (k >= 1 && k <= NPHASE)     ? k - 1 : -1;
        int lp = (k >= 2)                    ? k - 2 : -1;
        pipe_kernel<<<TOTAL_BLOCKS, 256>>>(pts, tgt, zp, sp, lp);
    }
    finalize_kernel<<<1, 1>>>(out);
}